// round 1
// baseline (speedup 1.0000x reference)
#include <cuda_runtime.h>
#include <math.h>

// Problem constants
#define BB   256
#define TT   1024
#define DD   256
#define UU   128
#define GG   384      // 3*U
#define MM   (BB*TT)  // 262144 rows

// Scratch (device globals — no allocation allowed)
__device__ float g_xproj[(size_t)MM * GG];   // [B*T, 384]  x @ input_kernel
__device__ float g_fg[(size_t)MM * UU];      // [B*T, 128]  sigmoid(sig @ fk + b_f)

// ---------------------------------------------------------------------------
// Kernel A: x_proj GEMM  C[M,384] = A[M,256] @ W[256,384]   (fp32 tiled SGEMM)
// tile 64x64, BK=16, 256 threads, 4x4 per thread
// ---------------------------------------------------------------------------
__global__ __launch_bounds__(256) void gemm_xproj(const float* __restrict__ A,
                                                  const float* __restrict__ W) {
    __shared__ float As[16][64];
    __shared__ float Ws[16][64];
    const int tid  = threadIdx.x;
    const int row0 = blockIdx.x * 64;
    const int col0 = blockIdx.y * 64;
    const int tr = tid >> 4;          // 0..15
    const int tc = tid & 15;          // 0..15

    const int ar  = tid >> 2;         // 0..63 (A tile row)
    const int ak4 = (tid & 3) << 2;   // 0,4,8,12
    const int wk  = tid >> 4;         // 0..15 (W tile k)
    const int wc4 = (tid & 15) << 2;  // 0..60

    float acc[4][4] = {};

    for (int k0 = 0; k0 < DD; k0 += 16) {
        float4 av = *(const float4*)&A[(size_t)(row0 + ar) * DD + k0 + ak4];
        As[ak4 + 0][ar] = av.x;
        As[ak4 + 1][ar] = av.y;
        As[ak4 + 2][ar] = av.z;
        As[ak4 + 3][ar] = av.w;
        *(float4*)&Ws[wk][wc4] =
            *(const float4*)&W[(size_t)(k0 + wk) * GG + col0 + wc4];
        __syncthreads();

#pragma unroll
        for (int k = 0; k < 16; ++k) {
            float a[4], b[4];
            *(float4*)a = *(const float4*)&As[k][tr << 2];
            *(float4*)b = *(const float4*)&Ws[k][tc << 2];
#pragma unroll
            for (int i = 0; i < 4; ++i)
#pragma unroll
                for (int j = 0; j < 4; ++j)
                    acc[i][j] = fmaf(a[i], b[j], acc[i][j]);
        }
        __syncthreads();
    }

#pragma unroll
    for (int i = 0; i < 4; ++i) {
        float4 v = make_float4(acc[i][0], acc[i][1], acc[i][2], acc[i][3]);
        *(float4*)&g_xproj[(size_t)(row0 + (tr << 2) + i) * GG + col0 + (tc << 2)] = v;
    }
}

// ---------------------------------------------------------------------------
// Kernel B: forget gates  f = sigmoid(sig[bt,20] @ fk[20,128] + b_f)
// ---------------------------------------------------------------------------
__global__ __launch_bounds__(256) void fgate_kernel(const float* __restrict__ sig,
                                                    const float* __restrict__ fk,
                                                    const float* __restrict__ bias) {
    const int idx = blockIdx.x * blockDim.x + threadIdx.x; // over B*T*U
    const int bt = idx >> 7;
    const int u  = idx & 127;
    float s = bias[UU + u];   // b_f
#pragma unroll
    for (int k = 0; k < 20; ++k)
        s = fmaf(__ldg(&sig[bt * 20 + k]), __ldg(&fk[k * UU + u]), s);
    g_fg[idx] = 1.0f / (1.0f + expf(-s));
}

// ---------------------------------------------------------------------------
// Kernel C: sequential scan. 128 blocks (2 batches each), 192 threads.
// recurrent_kernel resident in shared (192KB). Thread j owns gate columns
// 2j, 2j+1 for both batches.
// smem: srk[128*384] | hs float2[128] (h_b0,h_b1 interleaved) | gb[2][384]
// ---------------------------------------------------------------------------
#define SCAN_SMEM (196608 + 1024 + 3072)

__global__ __launch_bounds__(192) void scan_kernel(const float* __restrict__ rk,
                                                   const float* __restrict__ bias,
                                                   float* __restrict__ out) {
    extern __shared__ float smem[];
    float*  srk = smem;                       // 49152 floats
    float2* hs  = (float2*)(smem + 49152);    // 128 float2
    float*  gb  = smem + 49152 + 256;         // 768 floats: [2][384]

    const int j  = threadIdx.x;               // 0..191
    const int b0 = blockIdx.x * 2;
    const int b1 = b0 + 1;
    const int c0 = j << 1;                    // gate column pair base

    // load recurrent kernel into shared (coalesced float4)
    {
        const float4* rk4 = (const float4*)rk;
        float4* s4 = (float4*)srk;
        for (int i = j; i < (UU * GG) / 4; i += 192)
            s4[i] = rk4[i];
    }
    // init h
    if (j < UU) hs[j] = make_float2(0.f, 0.f);
    float cc0 = 0.f, cc1 = 0.f;

    // per-thread bias + activation region (columns c0,c0+1 share a region)
    const float bc0 = (c0 < UU) ? bias[c0] : bias[c0 + UU];
    const float bc1 = (c0 + 1 < UU) ? bias[c0 + 1] : bias[c0 + 1 + UU];
    const int region = c0 >> 7;  // 0:i(sig) 1:c_hat(tanh) 2:o(sig)

    __syncthreads();

    // preload t=0 operands
    float2 x0a = *(const float2*)&g_xproj[((size_t)b0 * TT) * GG + c0];
    float2 x1a = *(const float2*)&g_xproj[((size_t)b1 * TT) * GG + c0];
    float f0 = 0.f, f1 = 0.f;
    if (j < UU) {
        f0 = g_fg[((size_t)b0 * TT) * UU + j];
        f1 = g_fg[((size_t)b1 * TT) * UU + j];
    }

    const float4* hs4 = (const float4*)hs;

    for (int t = 0; t < TT; ++t) {
        // prefetch t+1 (consumed only after the long dot)
        const int tn = (t + 1 < TT) ? t + 1 : t;
        float2 nx0 = *(const float2*)&g_xproj[((size_t)b0 * TT + tn) * GG + c0];
        float2 nx1 = *(const float2*)&g_xproj[((size_t)b1 * TT + tn) * GG + c0];
        float nf0 = 0.f, nf1 = 0.f;
        if (j < UU) {
            nf0 = g_fg[((size_t)b0 * TT + tn) * UU + j];
            nf1 = g_fg[((size_t)b1 * TT + tn) * UU + j];
        }

        // gates = h_prev @ rk   (per thread: 2 cols x 2 batches)
        float a00 = 0.f, a01 = 0.f, a10 = 0.f, a11 = 0.f;
#pragma unroll 16
        for (int k = 0; k < UU; k += 2) {
            float4 h2 = hs4[k >> 1];                      // h0[k],h1[k],h0[k+1],h1[k+1]
            float2 w0 = *(const float2*)&srk[k * GG + c0];
            float2 w1 = *(const float2*)&srk[(k + 1) * GG + c0];
            a00 = fmaf(h2.x, w0.x, a00); a01 = fmaf(h2.x, w0.y, a01);
            a10 = fmaf(h2.y, w0.x, a10); a11 = fmaf(h2.y, w0.y, a11);
            a00 = fmaf(h2.z, w1.x, a00); a01 = fmaf(h2.z, w1.y, a01);
            a10 = fmaf(h2.w, w1.x, a10); a11 = fmaf(h2.w, w1.y, a11);
        }

        float p00 = a00 + x0a.x + bc0;
        float p01 = a01 + x0a.y + bc1;
        float p10 = a10 + x1a.x + bc0;
        float p11 = a11 + x1a.y + bc1;
        if (region == 1) {
            p00 = tanhf(p00); p01 = tanhf(p01);
            p10 = tanhf(p10); p11 = tanhf(p11);
        } else {
            p00 = 1.0f / (1.0f + expf(-p00));
            p01 = 1.0f / (1.0f + expf(-p01));
            p10 = 1.0f / (1.0f + expf(-p10));
            p11 = 1.0f / (1.0f + expf(-p11));
        }
        *(float2*)&gb[c0]       = make_float2(p00, p01);
        *(float2*)&gb[GG + c0]  = make_float2(p10, p11);

        __syncthreads();   // gates visible; all threads done reading hs

        if (j < UU) {
            float i0 = gb[j],       ch0 = gb[j + UU],       o0 = gb[j + 2 * UU];
            float i1 = gb[GG + j],  ch1 = gb[GG + j + UU],  o1 = gb[GG + j + 2 * UU];
            cc0 = fmaf(f0, cc0, i0 * ch0);
            cc1 = fmaf(f1, cc1, i1 * ch1);
            float h0v = o0 * tanhf(cc0);
            float h1v = o1 * tanhf(cc1);
            hs[j] = make_float2(h0v, h1v);
            out[((size_t)b0 * TT + t) * UU + j] = h0v;
            out[((size_t)b1 * TT + t) * UU + j] = h1v;
            f0 = nf0; f1 = nf1;
        }
        x0a = nx0; x1a = nx1;

        __syncthreads();   // hs ready for next step
    }
}

// ---------------------------------------------------------------------------
extern "C" void kernel_launch(void* const* d_in, const int* in_sizes, int n_in,
                              void* d_out, int out_size) {
    const float* inputs     = (const float*)d_in[0]; // [B,T,D]
    const float* signatures = (const float*)d_in[1]; // [B,T,SIG]
    const float* ikern      = (const float*)d_in[2]; // [D,3U]
    const float* rkern      = (const float*)d_in[3]; // [U,3U]
    const float* fkern      = (const float*)d_in[4]; // [SIG,U]
    const float* bias       = (const float*)d_in[5]; // [4U]
    float* out = (float*)d_out;                      // [B,T,U]

    (void)in_sizes; (void)n_in; (void)out_size;

    cudaFuncSetAttribute(scan_kernel,
                         cudaFuncAttributeMaxDynamicSharedMemorySize, SCAN_SMEM);

    gemm_xproj<<<dim3(MM / 64, GG / 64), 256>>>(inputs, ikern);
    fgate_kernel<<<(MM * UU) / 256, 256>>>(signatures, fkern, bias);
    scan_kernel<<<BB / 2, 192, SCAN_SMEM>>>(rkern, bias, out);
}

// round 3
// speedup vs baseline: 1.4630x; 1.4630x over previous
#include <cuda_runtime.h>
#include <cuda_bf16.h>
#include <math.h>
#include <stdint.h>

// Problem constants
#define BB   256
#define TT   1024
#define DD   256
#define UU   128
#define GG   384      // 3*U
#define MM   (BB*TT)  // 262144 rows

// Scratch (device globals — no allocation allowed)
__device__ float g_xproj[(size_t)MM * GG];        // [B*T, 384]
__device__ float g_fg[(size_t)MM * UU];           // [B*T, 128]
__device__ __nv_bfloat16 g_ahi[(size_t)MM * DD];  // bf16 hi split of inputs
__device__ __nv_bfloat16 g_alo[(size_t)MM * DD];  // bf16 lo split
__device__ __nv_bfloat16 g_bhi[(size_t)GG * DD];  // W^T hi: [384,256]
__device__ __nv_bfloat16 g_blo[(size_t)GG * DD];  // W^T lo

// ---------------------------------------------------------------------------
__device__ __forceinline__ uint32_t s2u(const void* p) {
    uint32_t a;
    asm("{ .reg .u64 t; cvta.to.shared.u64 t, %1; cvt.u32.u64 %0, t; }"
        : "=r"(a) : "l"(p));
    return a;
}

#define SW128(o) ((o) ^ (((o) >> 3) & 0x70))

__device__ __forceinline__ void ldsm_x4(uint32_t* r, uint32_t addr) {
    asm volatile("ldmatrix.sync.aligned.m8n8.x4.shared.b16 {%0,%1,%2,%3}, [%4];"
                 : "=r"(r[0]), "=r"(r[1]), "=r"(r[2]), "=r"(r[3]) : "r"(addr));
}

__device__ __forceinline__ void mma_bf16(float* d, const uint32_t* a,
                                         const uint32_t* b) {
    asm volatile(
        "mma.sync.aligned.m16n8k16.row.col.f32.bf16.bf16.f32 "
        "{%0,%1,%2,%3}, {%4,%5,%6,%7}, {%8,%9}, {%0,%1,%2,%3};"
        : "+f"(d[0]), "+f"(d[1]), "+f"(d[2]), "+f"(d[3])
        : "r"(a[0]), "r"(a[1]), "r"(a[2]), "r"(a[3]), "r"(b[0]), "r"(b[1]));
}

__device__ __forceinline__ void cp16(uint32_t dst, const void* src) {
    asm volatile("cp.async.cg.shared.global [%0], [%1], 16;"
                 :: "r"(dst), "l"(src) : "memory");
}
__device__ __forceinline__ void cp_commit() {
    asm volatile("cp.async.commit_group;" ::: "memory");
}
template <int N>
__device__ __forceinline__ void cp_wait() {
    asm volatile("cp.async.wait_group %0;" :: "n"(N) : "memory");
}

// fast activations (~1e-6 rel err, MUFU-based)
__device__ __forceinline__ float fsig(float x) {
    return __fdividef(1.0f, 1.0f + __expf(-x));
}
__device__ __forceinline__ float ftanh(float x) {
    return __fmaf_rn(2.0f, __fdividef(1.0f, 1.0f + __expf(-2.0f * x)), -1.0f);
}

// ---------------------------------------------------------------------------
// Split conversions
// ---------------------------------------------------------------------------
__global__ __launch_bounds__(256) void convert_a(const float* __restrict__ in) {
    size_t i = ((size_t)blockIdx.x * 256 + threadIdx.x) * 4;
    float4 v = *(const float4*)(in + i);
    float vv[4] = {v.x, v.y, v.z, v.w};
    unsigned short hb[4], lb[4];
#pragma unroll
    for (int j = 0; j < 4; ++j) {
        __nv_bfloat16 h = __float2bfloat16(vv[j]);
        __nv_bfloat16 l = __float2bfloat16(vv[j] - __bfloat162float(h));
        hb[j] = *reinterpret_cast<unsigned short*>(&h);
        lb[j] = *reinterpret_cast<unsigned short*>(&l);
    }
    uint2 ph, pl;
    ph.x = (uint32_t)hb[0] | ((uint32_t)hb[1] << 16);
    ph.y = (uint32_t)hb[2] | ((uint32_t)hb[3] << 16);
    pl.x = (uint32_t)lb[0] | ((uint32_t)lb[1] << 16);
    pl.y = (uint32_t)lb[2] | ((uint32_t)lb[3] << 16);
    *(uint2*)(g_ahi + i) = ph;
    *(uint2*)(g_alo + i) = pl;
}

// transpose + split input_kernel W[256,384] -> [384,256]
__global__ __launch_bounds__(256) void convert_b(const float* __restrict__ W) {
    int n = blockIdx.x;      // 0..383
    int k = threadIdx.x;     // 0..255
    float v = W[(size_t)k * GG + n];
    __nv_bfloat16 h = __float2bfloat16(v);
    __nv_bfloat16 l = __float2bfloat16(v - __bfloat162float(h));
    g_bhi[(size_t)n * DD + k] = h;
    g_blo[(size_t)n * DD + k] = l;
}

// ---------------------------------------------------------------------------
// HMMA GEMM: g_xproj[M,384] = A[M,256] @ W[256,384], 3-way bf16 split.
// CTA tile 128x128, BK=64, double-buffered cp.async.
// 8 warps: warp_m = wid/4 (2), warp_n = wid%4 (4); warp tile 64x32.
// smem per buffer: Ahi|Alo|Bhi|Blo tiles, each 128 rows x 128B (SW128).
// ---------------------------------------------------------------------------
#define GEMM_SMEM (2 * 4 * 16384)

__device__ __forceinline__ void load_tiles(uint32_t sb, char* gsm_unused,
                                           int buf, int k0, int row0, int n0g,
                                           int tid) {
    const uint32_t base = sb + buf * 65536;
#pragma unroll
    for (int i = 0; i < 4; ++i) {
        const int id  = tid + i * 256;
        const int row = id >> 3;
        const int c16 = id & 7;
        const uint32_t so = SW128((uint32_t)(row * 128 + c16 * 16));
        const size_t aoff = (size_t)(row0 + row) * DD + k0 + c16 * 8;
        const size_t boff = (size_t)(n0g + row) * DD + k0 + c16 * 8;
        cp16(base + so,                 g_ahi + aoff);
        cp16(base + 16384 + so,         g_alo + aoff);
        cp16(base + 32768 + so,         g_bhi + boff);
        cp16(base + 49152 + so,         g_blo + boff);
    }
}

__global__ __launch_bounds__(256, 1) void gemm_mma() {
    extern __shared__ char gsm[];
    const uint32_t sb = s2u(gsm);

    const int tid  = threadIdx.x;
    const int wid  = tid >> 5;
    const int lane = tid & 31;
    const int row0 = blockIdx.x * 128;
    const int n0g  = blockIdx.y * 128;

    const int m0w = (wid >> 2) * 64;   // 0 or 64
    const int n0w = (wid & 3) * 32;    // 0,32,64,96

    float acc[4][4][4];
#pragma unroll
    for (int i = 0; i < 4; ++i)
#pragma unroll
        for (int j = 0; j < 4; ++j)
#pragma unroll
            for (int k = 0; k < 4; ++k) acc[i][j][k] = 0.f;

    // per-lane ldmatrix address components
    const int a_lr = lane & 15;          // A row select within 16
    const int a_lc = (lane >> 4) * 16;   // A 16B col select
    const int b_lr = ((lane >> 4) << 3) + (lane & 7);  // B row select within 16
    const int b_lc = ((lane >> 3) & 1) * 16;           // B 16B col select

    load_tiles(sb, gsm, 0, 0, row0, n0g, tid);
    cp_commit();

#pragma unroll
    for (int c = 0; c < 4; ++c) {
        if (c < 3) {
            load_tiles(sb, gsm, (c + 1) & 1, (c + 1) * 64, row0, n0g, tid);
            cp_commit();
            cp_wait<1>();
        } else {
            cp_wait<0>();
        }
        __syncthreads();

        const uint32_t ab  = sb + (c & 1) * 65536;
        const uint32_t alb = ab + 16384;
        const uint32_t bhb = ab + 32768;
        const uint32_t blb = ab + 49152;

#pragma unroll
        for (int kf = 0; kf < 4; ++kf) {
            uint32_t ah[4][4], al[4][4], bh[2][4], bl[2][4];
#pragma unroll
            for (int mf = 0; mf < 4; ++mf) {
                const uint32_t off =
                    SW128((uint32_t)((m0w + mf * 16 + a_lr) * 128 + kf * 32 + a_lc));
                ldsm_x4(ah[mf], ab + off);
                ldsm_x4(al[mf], alb + off);
            }
#pragma unroll
            for (int nf2 = 0; nf2 < 2; ++nf2) {
                const uint32_t off =
                    SW128((uint32_t)((n0w + nf2 * 16 + b_lr) * 128 + kf * 32 + b_lc));
                ldsm_x4(bh[nf2], bhb + off);
                ldsm_x4(bl[nf2], blb + off);
            }
#pragma unroll
            for (int mf = 0; mf < 4; ++mf)
#pragma unroll
                for (int nf = 0; nf < 4; ++nf) {
                    const uint32_t* bhp = &bh[nf >> 1][(nf & 1) * 2];
                    const uint32_t* blp = &bl[nf >> 1][(nf & 1) * 2];
                    mma_bf16(acc[mf][nf], ah[mf], bhp);
                    mma_bf16(acc[mf][nf], ah[mf], blp);
                    mma_bf16(acc[mf][nf], al[mf], bhp);
                }
        }
        __syncthreads();
    }

    // epilogue: direct stores (float2 per C-tile half)
#pragma unroll
    for (int mf = 0; mf < 4; ++mf) {
        const int rg = row0 + m0w + mf * 16 + (lane >> 2);
#pragma unroll
        for (int nf = 0; nf < 4; ++nf) {
            const int cg = n0g + n0w + nf * 8 + ((lane & 3) << 1);
            *(float2*)&g_xproj[(size_t)rg * GG + cg] =
                make_float2(acc[mf][nf][0], acc[mf][nf][1]);
            *(float2*)&g_xproj[(size_t)(rg + 8) * GG + cg] =
                make_float2(acc[mf][nf][2], acc[mf][nf][3]);
        }
    }
}

// ---------------------------------------------------------------------------
// forget gates  f = sigmoid(sig[bt,20] @ fk[20,128] + b_f)
// ---------------------------------------------------------------------------
__global__ __launch_bounds__(256) void fgate_kernel(const float* __restrict__ sig,
                                                    const float* __restrict__ fk,
                                                    const float* __restrict__ bias) {
    const int idx = blockIdx.x * blockDim.x + threadIdx.x;
    const int bt = idx >> 7;
    const int u  = idx & 127;
    float s = bias[UU + u];
#pragma unroll
    for (int k = 0; k < 20; ++k)
        s = fmaf(__ldg(&sig[bt * 20 + k]), __ldg(&fk[k * UU + u]), s);
    g_fg[idx] = fsig(s);
}

// ---------------------------------------------------------------------------
// Sequential scan. 128 blocks (2 batches each), 192 threads.
// ---------------------------------------------------------------------------
#define SCAN_SMEM (196608 + 1024 + 3072)

__global__ __launch_bounds__(192) void scan_kernel(const float* __restrict__ rk,
                                                   const float* __restrict__ bias,
                                                   float* __restrict__ out) {
    extern __shared__ float smemf[];
    float*  srk = smemf;
    float2* hs  = (float2*)(smemf + 49152);
    float*  gb  = smemf + 49152 + 256;

    const int j  = threadIdx.x;
    const int b0 = blockIdx.x * 2;
    const int b1 = b0 + 1;
    const int c0 = j << 1;

    {
        const float4* rk4 = (const float4*)rk;
        float4* s4 = (float4*)srk;
        for (int i = j; i < (UU * GG) / 4; i += 192)
            s4[i] = rk4[i];
    }
    if (j < UU) hs[j] = make_float2(0.f, 0.f);
    float cc0 = 0.f, cc1 = 0.f;

    const float bc0 = (c0 < UU) ? bias[c0] : bias[c0 + UU];
    const float bc1 = (c0 + 1 < UU) ? bias[c0 + 1] : bias[c0 + 1 + UU];
    const int region = c0 >> 7;

    __syncthreads();

    float2 x0a = *(const float2*)&g_xproj[((size_t)b0 * TT) * GG + c0];
    float2 x1a = *(const float2*)&g_xproj[((size_t)b1 * TT) * GG + c0];
    float f0 = 0.f, f1 = 0.f;
    if (j < UU) {
        f0 = g_fg[((size_t)b0 * TT) * UU + j];
        f1 = g_fg[((size_t)b1 * TT) * UU + j];
    }

    const float4* hs4 = (const float4*)hs;

    for (int t = 0; t < TT; ++t) {
        const int tn = (t + 1 < TT) ? t + 1 : t;
        float2 nx0 = *(const float2*)&g_xproj[((size_t)b0 * TT + tn) * GG + c0];
        float2 nx1 = *(const float2*)&g_xproj[((size_t)b1 * TT + tn) * GG + c0];
        float nf0 = 0.f, nf1 = 0.f;
        if (j < UU) {
            nf0 = g_fg[((size_t)b0 * TT + tn) * UU + j];
            nf1 = g_fg[((size_t)b1 * TT + tn) * UU + j];
        }

        float a00 = 0.f, a01 = 0.f, a10 = 0.f, a11 = 0.f;
#pragma unroll 16
        for (int k = 0; k < UU; k += 2) {
            float4 h2 = hs4[k >> 1];
            float2 w0 = *(const float2*)&srk[k * GG + c0];
            float2 w1 = *(const float2*)&srk[(k + 1) * GG + c0];
            a00 = fmaf(h2.x, w0.x, a00); a01 = fmaf(h2.x, w0.y, a01);
            a10 = fmaf(h2.y, w0.x, a10); a11 = fmaf(h2.y, w0.y, a11);
            a00 = fmaf(h2.z, w1.x, a00); a01 = fmaf(h2.z, w1.y, a01);
            a10 = fmaf(h2.w, w1.x, a10); a11 = fmaf(h2.w, w1.y, a11);
        }

        float p00 = a00 + x0a.x + bc0;
        float p01 = a01 + x0a.y + bc1;
        float p10 = a10 + x1a.x + bc0;
        float p11 = a11 + x1a.y + bc1;
        if (region == 1) {
            p00 = ftanh(p00); p01 = ftanh(p01);
            p10 = ftanh(p10); p11 = ftanh(p11);
        } else {
            p00 = fsig(p00); p01 = fsig(p01);
            p10 = fsig(p10); p11 = fsig(p11);
        }
        *(float2*)&gb[c0]      = make_float2(p00, p01);
        *(float2*)&gb[GG + c0] = make_float2(p10, p11);

        __syncthreads();

        if (j < UU) {
            float i0 = gb[j],      ch0 = gb[j + UU],      o0 = gb[j + 2 * UU];
            float i1 = gb[GG + j], ch1 = gb[GG + j + UU], o1 = gb[GG + j + 2 * UU];
            cc0 = fmaf(f0, cc0, i0 * ch0);
            cc1 = fmaf(f1, cc1, i1 * ch1);
            float h0v = o0 * ftanh(cc0);
            float h1v = o1 * ftanh(cc1);
            hs[j] = make_float2(h0v, h1v);
            out[((size_t)b0 * TT + t) * UU + j] = h0v;
            out[((size_t)b1 * TT + t) * UU + j] = h1v;
            f0 = nf0; f1 = nf1;
        }
        x0a = nx0; x1a = nx1;

        __syncthreads();
    }
}

// ---------------------------------------------------------------------------
extern "C" void kernel_launch(void* const* d_in, const int* in_sizes, int n_in,
                              void* d_out, int out_size) {
    const float* inputs     = (const float*)d_in[0];
    const float* signatures = (const float*)d_in[1];
    const float* ikern      = (const float*)d_in[2];
    const float* rkern      = (const float*)d_in[3];
    const float* fkern      = (const float*)d_in[4];
    const float* bias       = (const float*)d_in[5];
    float* out = (float*)d_out;

    (void)in_sizes; (void)n_in; (void)out_size;

    cudaFuncSetAttribute(gemm_mma,
                         cudaFuncAttributeMaxDynamicSharedMemorySize, GEMM_SMEM);
    cudaFuncSetAttribute(scan_kernel,
                         cudaFuncAttributeMaxDynamicSharedMemorySize, SCAN_SMEM);

    convert_a<<<(MM * DD) / 4 / 256, 256>>>(inputs);
    convert_b<<<GG, DD>>>(ikern);
    fgate_kernel<<<(MM * UU) / 256, 256>>>(signatures, fkern, bias);
    gemm_mma<<<dim3(MM / 128, GG / 128), 256, GEMM_SMEM>>>();
    scan_kernel<<<BB / 2, 192, SCAN_SMEM>>>(rkern, bias, out);
}

// round 4
// speedup vs baseline: 2.1020x; 1.4368x over previous
#include <cuda_runtime.h>
#include <cuda_bf16.h>
#include <math.h>
#include <stdint.h>

// Problem constants
#define BB   256
#define TT   1024
#define DD   256
#define UU   128
#define GG   384      // 3*U
#define MM   (BB*TT)  // 262144 rows

// Scratch (device globals — no allocation allowed)
__device__ float g_xproj[(size_t)MM * GG];        // [B*T, 384]
__device__ float g_fg[(size_t)MM * UU];           // [B*T, 128]
__device__ __nv_bfloat16 g_ahi[(size_t)MM * DD];  // bf16 hi split of inputs
__device__ __nv_bfloat16 g_alo[(size_t)MM * DD];  // bf16 lo split
__device__ __nv_bfloat16 g_bhi[(size_t)GG * DD];  // W^T hi: [384,256]
__device__ __nv_bfloat16 g_blo[(size_t)GG * DD];  // W^T lo
__device__ __nv_bfloat16 g_rk[(size_t)GG * UU];   // rk^T bf16 hi: [384,128]

// ---------------------------------------------------------------------------
__device__ __forceinline__ uint32_t s2u(const void* p) {
    uint32_t a;
    asm("{ .reg .u64 t; cvta.to.shared.u64 t, %1; cvt.u32.u64 %0, t; }"
        : "=r"(a) : "l"(p));
    return a;
}

#define SW128(o) ((o) ^ (((o) >> 3) & 0x70))

__device__ __forceinline__ void ldsm_x4(uint32_t* r, uint32_t addr) {
    asm volatile("ldmatrix.sync.aligned.m8n8.x4.shared.b16 {%0,%1,%2,%3}, [%4];"
                 : "=r"(r[0]), "=r"(r[1]), "=r"(r[2]), "=r"(r[3]) : "r"(addr));
}

__device__ __forceinline__ void mma_bf16(float* d, const uint32_t* a,
                                         const uint32_t* b) {
    asm volatile(
        "mma.sync.aligned.m16n8k16.row.col.f32.bf16.bf16.f32 "
        "{%0,%1,%2,%3}, {%4,%5,%6,%7}, {%8,%9}, {%0,%1,%2,%3};"
        : "+f"(d[0]), "+f"(d[1]), "+f"(d[2]), "+f"(d[3])
        : "r"(a[0]), "r"(a[1]), "r"(a[2]), "r"(a[3]), "r"(b[0]), "r"(b[1]));
}

__device__ __forceinline__ void cp16(uint32_t dst, const void* src) {
    asm volatile("cp.async.cg.shared.global [%0], [%1], 16;"
                 :: "r"(dst), "l"(src) : "memory");
}
__device__ __forceinline__ void cp_commit() {
    asm volatile("cp.async.commit_group;" ::: "memory");
}
template <int N>
__device__ __forceinline__ void cp_wait() {
    asm volatile("cp.async.wait_group %0;" :: "n"(N) : "memory");
}

__device__ __forceinline__ float tanh_apx(float x) {
    float y;
    asm("tanh.approx.f32 %0, %1;" : "=f"(y) : "f"(x));
    return y;
}
__device__ __forceinline__ float fsig(float x) {
    return __fdividef(1.0f, 1.0f + __expf(-x));
}

// ---------------------------------------------------------------------------
// Split conversions
// ---------------------------------------------------------------------------
__global__ __launch_bounds__(256) void convert_a(const float* __restrict__ in) {
    size_t i = ((size_t)blockIdx.x * 256 + threadIdx.x) * 4;
    float4 v = *(const float4*)(in + i);
    float vv[4] = {v.x, v.y, v.z, v.w};
    unsigned short hb[4], lb[4];
#pragma unroll
    for (int j = 0; j < 4; ++j) {
        __nv_bfloat16 h = __float2bfloat16(vv[j]);
        __nv_bfloat16 l = __float2bfloat16(vv[j] - __bfloat162float(h));
        hb[j] = *reinterpret_cast<unsigned short*>(&h);
        lb[j] = *reinterpret_cast<unsigned short*>(&l);
    }
    uint2 ph, pl;
    ph.x = (uint32_t)hb[0] | ((uint32_t)hb[1] << 16);
    ph.y = (uint32_t)hb[2] | ((uint32_t)hb[3] << 16);
    pl.x = (uint32_t)lb[0] | ((uint32_t)lb[1] << 16);
    pl.y = (uint32_t)lb[2] | ((uint32_t)lb[3] << 16);
    *(uint2*)(g_ahi + i) = ph;
    *(uint2*)(g_alo + i) = pl;
}

// transpose + split input_kernel W[256,384] -> [384,256]
__global__ __launch_bounds__(256) void convert_b(const float* __restrict__ W) {
    int n = blockIdx.x;      // 0..383
    int k = threadIdx.x;     // 0..255
    float v = W[(size_t)k * GG + n];
    __nv_bfloat16 h = __float2bfloat16(v);
    __nv_bfloat16 l = __float2bfloat16(v - __bfloat162float(h));
    g_bhi[(size_t)n * DD + k] = h;
    g_blo[(size_t)n * DD + k] = l;
}

// transpose recurrent_kernel rk[128,384] -> bf16 [384,128]
__global__ __launch_bounds__(128) void convert_rk(const float* __restrict__ rk) {
    int n = blockIdx.x;      // 0..383
    int k = threadIdx.x;     // 0..127
    g_rk[(size_t)n * UU + k] = __float2bfloat16(rk[(size_t)k * GG + n]);
}

// ---------------------------------------------------------------------------
// HMMA GEMM: g_xproj[M,384] = A[M,256] @ W[256,384], 3-way bf16 split.
// ---------------------------------------------------------------------------
#define GEMM_SMEM (2 * 4 * 16384)

__device__ __forceinline__ void load_tiles(uint32_t sb, int buf, int k0,
                                           int row0, int n0g, int tid) {
    const uint32_t base = sb + buf * 65536;
#pragma unroll
    for (int i = 0; i < 4; ++i) {
        const int id  = tid + i * 256;
        const int row = id >> 3;
        const int c16 = id & 7;
        const uint32_t so = SW128((uint32_t)(row * 128 + c16 * 16));
        const size_t aoff = (size_t)(row0 + row) * DD + k0 + c16 * 8;
        const size_t boff = (size_t)(n0g + row) * DD + k0 + c16 * 8;
        cp16(base + so,         g_ahi + aoff);
        cp16(base + 16384 + so, g_alo + aoff);
        cp16(base + 32768 + so, g_bhi + boff);
        cp16(base + 49152 + so, g_blo + boff);
    }
}

__global__ __launch_bounds__(256, 1) void gemm_mma() {
    extern __shared__ char gsm[];
    const uint32_t sb = s2u(gsm);

    const int tid  = threadIdx.x;
    const int wid  = tid >> 5;
    const int lane = tid & 31;
    const int row0 = blockIdx.x * 128;
    const int n0g  = blockIdx.y * 128;

    const int m0w = (wid >> 2) * 64;
    const int n0w = (wid & 3) * 32;

    float acc[4][4][4];
#pragma unroll
    for (int i = 0; i < 4; ++i)
#pragma unroll
        for (int j = 0; j < 4; ++j)
#pragma unroll
            for (int k = 0; k < 4; ++k) acc[i][j][k] = 0.f;

    const int a_lr = lane & 15;
    const int a_lc = (lane >> 4) * 16;
    const int b_lr = ((lane >> 4) << 3) + (lane & 7);
    const int b_lc = ((lane >> 3) & 1) * 16;

    load_tiles(sb, 0, 0, row0, n0g, tid);
    cp_commit();

#pragma unroll
    for (int c = 0; c < 4; ++c) {
        if (c < 3) {
            load_tiles(sb, (c + 1) & 1, (c + 1) * 64, row0, n0g, tid);
            cp_commit();
            cp_wait<1>();
        } else {
            cp_wait<0>();
        }
        __syncthreads();

        const uint32_t ab  = sb + (c & 1) * 65536;
        const uint32_t alb = ab + 16384;
        const uint32_t bhb = ab + 32768;
        const uint32_t blb = ab + 49152;

#pragma unroll
        for (int kf = 0; kf < 4; ++kf) {
            uint32_t ah[4][4], al[4][4], bh[2][4], bl[2][4];
#pragma unroll
            for (int mf = 0; mf < 4; ++mf) {
                const uint32_t off =
                    SW128((uint32_t)((m0w + mf * 16 + a_lr) * 128 + kf * 32 + a_lc));
                ldsm_x4(ah[mf], ab + off);
                ldsm_x4(al[mf], alb + off);
            }
#pragma unroll
            for (int nf2 = 0; nf2 < 2; ++nf2) {
                const uint32_t off =
                    SW128((uint32_t)((n0w + nf2 * 16 + b_lr) * 128 + kf * 32 + b_lc));
                ldsm_x4(bh[nf2], bhb + off);
                ldsm_x4(bl[nf2], blb + off);
            }
#pragma unroll
            for (int mf = 0; mf < 4; ++mf)
#pragma unroll
                for (int nf = 0; nf < 4; ++nf) {
                    const uint32_t* bhp = &bh[nf >> 1][(nf & 1) * 2];
                    const uint32_t* blp = &bl[nf >> 1][(nf & 1) * 2];
                    mma_bf16(acc[mf][nf], ah[mf], bhp);
                    mma_bf16(acc[mf][nf], ah[mf], blp);
                    mma_bf16(acc[mf][nf], al[mf], bhp);
                }
        }
        __syncthreads();
    }

#pragma unroll
    for (int mf = 0; mf < 4; ++mf) {
        const int rg = row0 + m0w + mf * 16 + (lane >> 2);
#pragma unroll
        for (int nf = 0; nf < 4; ++nf) {
            const int cg = n0g + n0w + nf * 8 + ((lane & 3) << 1);
            *(float2*)&g_xproj[(size_t)rg * GG + cg] =
                make_float2(acc[mf][nf][0], acc[mf][nf][1]);
            *(float2*)&g_xproj[(size_t)(rg + 8) * GG + cg] =
                make_float2(acc[mf][nf][2], acc[mf][nf][3]);
        }
    }
}

// ---------------------------------------------------------------------------
// forget gates
// ---------------------------------------------------------------------------
__global__ __launch_bounds__(256) void fgate_kernel(const float* __restrict__ sig,
                                                    const float* __restrict__ fk,
                                                    const float* __restrict__ bias) {
    const int idx = blockIdx.x * blockDim.x + threadIdx.x;
    const int bt = idx >> 7;
    const int u  = idx & 127;
    float s = bias[UU + u];
#pragma unroll
    for (int k = 0; k < 20; ++k)
        s = fmaf(__ldg(&sig[bt * 20 + k]), __ldg(&fk[k * UU + u]), s);
    g_fg[idx] = fsig(s);
}

// ---------------------------------------------------------------------------
// HMMA scan: 32 blocks x 8 batches, 256 threads (8 warps).
// Warp w owns gate cols [w*48, w*48+48). rk bf16-hi held in registers as
// m16n8k16 B-fragments. A rows 0-7 = h_hi(batch), rows 8-15 = h_lo(batch);
// gate = acc[r] + acc[r+8] recovers full precision.
// smem (floats): xs 2*8*392 | fs 2*8*132 | gs 8*392 | As(u32) 16*68
// ---------------------------------------------------------------------------
#define XS_F   3136          // 8*392
#define FS_F   1056          // 8*132
#define GS_F   3136
#define AS_W   1088          // 16*68
#define SCAN_SMEM ((2*XS_F + 2*FS_F + GS_F + AS_W) * 4)
#define XS_OFF 0
#define FS_OFF (2*XS_F)
#define GS_OFF (2*XS_F + 2*FS_F)
#define AS_OFF (2*XS_F + 2*FS_F + GS_F)

__global__ __launch_bounds__(256, 1) void scan_mma(const float* __restrict__ bias,
                                                   float* __restrict__ out) {
    extern __shared__ float sm[];
    float* xs = sm + XS_OFF;
    float* fs = sm + FS_OFF;
    float* gs = sm + GS_OFF;
    uint32_t* As = (uint32_t*)(sm + AS_OFF);
    const uint32_t smu = s2u(sm);

    const int tid  = threadIdx.x;
    const int wid  = tid >> 5;
    const int lane = tid & 31;
    const int b0g  = blockIdx.x * 8;
    const int n0w  = wid * 48;

    // zero A (h0 = 0)
    for (int i = tid; i < AS_W; i += 256) As[i] = 0;

    // rk fragments: wfr[kc][nc] covers k=[kc*16,+16), n=[n0w+nc*8,+8)
    uint32_t wfr[8][6][2];
#pragma unroll
    for (int kc = 0; kc < 8; ++kc)
#pragma unroll
        for (int nc = 0; nc < 6; ++nc) {
            const int n = n0w + nc * 8 + (lane >> 2);
            const int k = kc * 16 + (lane & 3) * 2;
            wfr[kc][nc][0] = *(const uint32_t*)&g_rk[(size_t)n * UU + k];
            wfr[kc][nc][1] = *(const uint32_t*)&g_rk[(size_t)n * UU + k + 8];
        }

    // per-nc constants (acc layout: n = n0w + nc*8 + (lane&3)*2)
    float bb0[6], bb1[6], pp[6];
#pragma unroll
    for (int nc = 0; nc < 6; ++nc) {
        const int n = n0w + nc * 8 + (lane & 3) * 2;
        bb0[nc] = (n < UU) ? bias[n] : bias[n + UU];
        bb1[nc] = (n + 1 < UU) ? bias[n + 1] : bias[n + 1 + UU];
        pp[nc]  = ((n >> 7) == 1) ? 1.0f : 0.5f;   // tanh region: scale 1
    }

    // combine mapping: thread handles (b, u2) and (b+4, u2)
    const int cb = tid >> 6;     // 0..3
    const int u2 = tid & 63;
    float cst[2][2] = {{0.f, 0.f}, {0.f, 0.f}};

    // prefetch step t into buffer t&1
    const int xr = tid >> 5, xo = tid & 31;   // f-chunk coords
#define PREFETCH(t)                                                            \
    {                                                                          \
        const int _buf = (t) & 1;                                              \
        _Pragma("unroll")                                                      \
        for (int k2 = 0; k2 < 3; ++k2) {                                       \
            const int id = tid + k2 * 256;                                     \
            const int r = id / 96, o = id % 96;                                \
            cp16(smu + (XS_OFF + _buf * XS_F + r * 392 + o * 4) * 4,           \
                 &g_xproj[((size_t)(b0g + r) * TT + (t)) * GG + o * 4]);       \
        }                                                                      \
        cp16(smu + (FS_OFF + _buf * FS_F + xr * 132 + xo * 4) * 4,             \
             &g_fg[((size_t)(b0g + xr) * TT + (t)) * UU + xo * 4]);            \
        cp_commit();                                                           \
    }

    PREFETCH(0);

    const int arow = (lane >> 2) * 68 + (lane & 3);
    for (int t = 0; t < TT; ++t) {
        cp_wait<0>();
        __syncthreads();     // x/f ready; prev combine's As/gs ordered

        // acc init from x_proj
        const float* xb = xs + (t & 1) * XS_F + (lane >> 2) * 392;
        float acc[6][4];
#pragma unroll
        for (int nc = 0; nc < 6; ++nc) {
            const float2 xv = *(const float2*)&xb[n0w + nc * 8 + (lane & 3) * 2];
            acc[nc][0] = xv.x; acc[nc][1] = xv.y;
            acc[nc][2] = 0.f;  acc[nc][3] = 0.f;
        }

        if (t + 1 < TT) PREFETCH(t + 1);

        // gates = [h_hi; h_lo] @ rk
#pragma unroll
        for (int kc = 0; kc < 8; ++kc) {
            uint32_t af[4];
            const int base = arow + kc * 8;
            af[0] = As[base];
            af[1] = As[base + 8 * 68];
            af[2] = As[base + 4];
            af[3] = As[base + 8 * 68 + 4];
#pragma unroll
            for (int nc = 0; nc < 6; ++nc)
                mma_bf16(acc[nc], af, wfr[kc][nc]);
        }

        // fold + bias + activation -> gs
        float* gr = gs + (lane >> 2) * 392;
#pragma unroll
        for (int nc = 0; nc < 6; ++nc) {
            const float p = pp[nc], q = 1.0f - p;
            const float g0 = acc[nc][0] + acc[nc][2] + bb0[nc];
            const float g1 = acc[nc][1] + acc[nc][3] + bb1[nc];
            const float v0 = tanh_apx(g0 * p);
            const float v1 = tanh_apx(g1 * p);
            *(float2*)&gr[n0w + nc * 8 + (lane & 3) * 2] =
                make_float2(fmaf(v0, p, q), fmaf(v1, p, q));
        }
        __syncthreads();

        // combine: c update, h out, write h_hi/h_lo back as A rows
#pragma unroll
        for (int it = 0; it < 2; ++it) {
            const int b = cb + it * 4;
            const float* gbp = gs + b * 392 + u2 * 2;
            const float2 iv = *(const float2*)&gbp[0];
            const float2 cv = *(const float2*)&gbp[UU];
            const float2 ov = *(const float2*)&gbp[2 * UU];
            const float2 fv =
                *(const float2*)&fs[(t & 1) * FS_F + b * 132 + u2 * 2];
            const float cn0 = fmaf(fv.x, cst[it][0], iv.x * cv.x);
            const float cn1 = fmaf(fv.y, cst[it][1], iv.y * cv.y);
            cst[it][0] = cn0; cst[it][1] = cn1;
            const float h0 = ov.x * tanh_apx(cn0);
            const float h1 = ov.y * tanh_apx(cn1);
            *(float2*)&out[((size_t)(b0g + b) * TT + t) * UU + u2 * 2] =
                make_float2(h0, h1);
            const __nv_bfloat16 h0h = __float2bfloat16(h0);
            const __nv_bfloat16 h1h = __float2bfloat16(h1);
            const __nv_bfloat16 h0l =
                __float2bfloat16(h0 - __bfloat162float(h0h));
            const __nv_bfloat16 h1l =
                __float2bfloat16(h1 - __bfloat162float(h1h));
            const uint32_t phi = (uint32_t)*(const unsigned short*)&h0h |
                                 ((uint32_t)*(const unsigned short*)&h1h << 16);
            const uint32_t plo = (uint32_t)*(const unsigned short*)&h0l |
                                 ((uint32_t)*(const unsigned short*)&h1l << 16);
            As[b * 68 + u2]       = phi;
            As[(b + 8) * 68 + u2] = plo;
        }
    }
}

// ---------------------------------------------------------------------------
extern "C" void kernel_launch(void* const* d_in, const int* in_sizes, int n_in,
                              void* d_out, int out_size) {
    const float* inputs     = (const float*)d_in[0];
    const float* signatures = (const float*)d_in[1];
    const float* ikern      = (const float*)d_in[2];
    const float* rkern      = (const float*)d_in[3];
    const float* fkern      = (const float*)d_in[4];
    const float* bias       = (const float*)d_in[5];
    float* out = (float*)d_out;

    (void)in_sizes; (void)n_in; (void)out_size;

    cudaFuncSetAttribute(gemm_mma,
                         cudaFuncAttributeMaxDynamicSharedMemorySize, GEMM_SMEM);
    cudaFuncSetAttribute(scan_mma,
                         cudaFuncAttributeMaxDynamicSharedMemorySize, SCAN_SMEM);

    convert_a<<<(MM * DD) / 4 / 256, 256>>>(inputs);
    convert_b<<<GG, DD>>>(ikern);
    convert_rk<<<GG, UU>>>(rkern);
    fgate_kernel<<<(MM * UU) / 256, 256>>>(signatures, fkern, bias);
    gemm_mma<<<dim3(MM / 128, GG / 128), 256, GEMM_SMEM>>>();
    scan_mma<<<32, 256, SCAN_SMEM>>>(bias, out);
}

// round 6
// speedup vs baseline: 2.2295x; 1.0607x over previous
#include <cuda_runtime.h>
#include <cuda_bf16.h>
#include <math.h>
#include <stdint.h>

// Problem constants
#define BB   256
#define TT   1024
#define DD   256
#define UU   128
#define GG   384      // 3*U
#define MM   (BB*TT)  // 262144 rows

// Scratch (device globals — no allocation allowed)
__device__ float g_xproj[(size_t)MM * GG];        // [B*T, 384]
__device__ float g_fg[(size_t)MM * UU];           // [B*T, 128]
__device__ __nv_bfloat16 g_ahi[(size_t)MM * DD];  // bf16 hi split of inputs
__device__ __nv_bfloat16 g_alo[(size_t)MM * DD];  // bf16 lo split
__device__ __nv_bfloat16 g_bhi[(size_t)GG * DD];  // W^T hi: [384,256]
__device__ __nv_bfloat16 g_blo[(size_t)GG * DD];  // W^T lo
__device__ __nv_bfloat16 g_rk[(size_t)GG * UU];   // rk^T bf16 hi: [384,128]

// ---------------------------------------------------------------------------
__device__ __forceinline__ uint32_t s2u(const void* p) {
    uint32_t a;
    asm("{ .reg .u64 t; cvta.to.shared.u64 t, %1; cvt.u32.u64 %0, t; }"
        : "=r"(a) : "l"(p));
    return a;
}

#define SW128(o) ((o) ^ (((o) >> 3) & 0x70))

__device__ __forceinline__ void ldsm_x4(uint32_t* r, uint32_t addr) {
    asm volatile("ldmatrix.sync.aligned.m8n8.x4.shared.b16 {%0,%1,%2,%3}, [%4];"
                 : "=r"(r[0]), "=r"(r[1]), "=r"(r[2]), "=r"(r[3]) : "r"(addr));
}

__device__ __forceinline__ void mma_bf16(float* d, const uint32_t* a,
                                         const uint32_t* b) {
    asm volatile(
        "mma.sync.aligned.m16n8k16.row.col.f32.bf16.bf16.f32 "
        "{%0,%1,%2,%3}, {%4,%5,%6,%7}, {%8,%9}, {%0,%1,%2,%3};"
        : "+f"(d[0]), "+f"(d[1]), "+f"(d[2]), "+f"(d[3])
        : "r"(a[0]), "r"(a[1]), "r"(a[2]), "r"(a[3]), "r"(b[0]), "r"(b[1]));
}

__device__ __forceinline__ void cp16(uint32_t dst, const void* src) {
    asm volatile("cp.async.cg.shared.global [%0], [%1], 16;"
                 :: "r"(dst), "l"(src) : "memory");
}
__device__ __forceinline__ void cp_commit() {
    asm volatile("cp.async.commit_group;" ::: "memory");
}
template <int N>
__device__ __forceinline__ void cp_wait() {
    asm volatile("cp.async.wait_group %0;" :: "n"(N) : "memory");
}

__device__ __forceinline__ float tanh_apx(float x) {
    float y;
    asm("tanh.approx.f32 %0, %1;" : "=f"(y) : "f"(x));
    return y;
}
__device__ __forceinline__ float fsig(float x) {
    return __fdividef(1.0f, 1.0f + __expf(-x));
}

// ---------------------------------------------------------------------------
// Split conversions
// ---------------------------------------------------------------------------
__global__ __launch_bounds__(256) void convert_a(const float* __restrict__ in) {
    size_t i = ((size_t)blockIdx.x * 256 + threadIdx.x) * 4;
    float4 v = *(const float4*)(in + i);
    float vv[4] = {v.x, v.y, v.z, v.w};
    unsigned short hb[4], lb[4];
#pragma unroll
    for (int j = 0; j < 4; ++j) {
        __nv_bfloat16 h = __float2bfloat16(vv[j]);
        __nv_bfloat16 l = __float2bfloat16(vv[j] - __bfloat162float(h));
        hb[j] = *reinterpret_cast<unsigned short*>(&h);
        lb[j] = *reinterpret_cast<unsigned short*>(&l);
    }
    uint2 ph, pl;
    ph.x = (uint32_t)hb[0] | ((uint32_t)hb[1] << 16);
    ph.y = (uint32_t)hb[2] | ((uint32_t)hb[3] << 16);
    pl.x = (uint32_t)lb[0] | ((uint32_t)lb[1] << 16);
    pl.y = (uint32_t)lb[2] | ((uint32_t)lb[3] << 16);
    *(uint2*)(g_ahi + i) = ph;
    *(uint2*)(g_alo + i) = pl;
}

// transpose + split input_kernel W[256,384] -> [384,256]
__global__ __launch_bounds__(256) void convert_b(const float* __restrict__ W) {
    int n = blockIdx.x;
    int k = threadIdx.x;
    float v = W[(size_t)k * GG + n];
    __nv_bfloat16 h = __float2bfloat16(v);
    __nv_bfloat16 l = __float2bfloat16(v - __bfloat162float(h));
    g_bhi[(size_t)n * DD + k] = h;
    g_blo[(size_t)n * DD + k] = l;
}

// transpose recurrent_kernel rk[128,384] -> bf16 [384,128]
__global__ __launch_bounds__(128) void convert_rk(const float* __restrict__ rk) {
    int n = blockIdx.x;
    int k = threadIdx.x;
    g_rk[(size_t)n * UU + k] = __float2bfloat16(rk[(size_t)k * GG + n]);
}

// ---------------------------------------------------------------------------
// HMMA GEMM: g_xproj[M,384] = A[M,256] @ W[256,384], 3-way bf16 split.
// grid: x = N-tile (3), y = M-tile (2048) -> 3 adjacent blocks share A in L2.
// ---------------------------------------------------------------------------
#define GEMM_SMEM (2 * 4 * 16384)

__device__ __forceinline__ void load_tiles(uint32_t sb, int buf, int k0,
                                           int row0, int n0g, int tid) {
    const uint32_t base = sb + buf * 65536;
#pragma unroll
    for (int i = 0; i < 4; ++i) {
        const int id  = tid + i * 256;
        const int row = id >> 3;
        const int c16 = id & 7;
        const uint32_t so = SW128((uint32_t)(row * 128 + c16 * 16));
        const size_t aoff = (size_t)(row0 + row) * DD + k0 + c16 * 8;
        const size_t boff = (size_t)(n0g + row) * DD + k0 + c16 * 8;
        cp16(base + so,         g_ahi + aoff);
        cp16(base + 16384 + so, g_alo + aoff);
        cp16(base + 32768 + so, g_bhi + boff);
        cp16(base + 49152 + so, g_blo + boff);
    }
}

__global__ __launch_bounds__(256, 1) void gemm_mma() {
    extern __shared__ char gsm[];
    const uint32_t sb = s2u(gsm);

    const int tid  = threadIdx.x;
    const int wid  = tid >> 5;
    const int lane = tid & 31;
    const int n0g  = blockIdx.x * 128;
    const int row0 = blockIdx.y * 128;

    const int m0w = (wid >> 2) * 64;
    const int n0w = (wid & 3) * 32;

    float acc[4][4][4];
#pragma unroll
    for (int i = 0; i < 4; ++i)
#pragma unroll
        for (int j = 0; j < 4; ++j)
#pragma unroll
            for (int k = 0; k < 4; ++k) acc[i][j][k] = 0.f;

    const int a_lr = lane & 15;
    const int a_lc = (lane >> 4) * 16;
    const int b_lr = ((lane >> 4) << 3) + (lane & 7);
    const int b_lc = ((lane >> 3) & 1) * 16;

    load_tiles(sb, 0, 0, row0, n0g, tid);
    cp_commit();

#pragma unroll
    for (int c = 0; c < 4; ++c) {
        if (c < 3) {
            load_tiles(sb, (c + 1) & 1, (c + 1) * 64, row0, n0g, tid);
            cp_commit();
            cp_wait<1>();
        } else {
            cp_wait<0>();
        }
        __syncthreads();

        const uint32_t ab  = sb + (c & 1) * 65536;
        const uint32_t alb = ab + 16384;
        const uint32_t bhb = ab + 32768;
        const uint32_t blb = ab + 49152;

#pragma unroll
        for (int kf = 0; kf < 4; ++kf) {
            uint32_t ah[4][4], al[4][4], bh[2][4], bl[2][4];
#pragma unroll
            for (int mf = 0; mf < 4; ++mf) {
                const uint32_t off =
                    SW128((uint32_t)((m0w + mf * 16 + a_lr) * 128 + kf * 32 + a_lc));
                ldsm_x4(ah[mf], ab + off);
                ldsm_x4(al[mf], alb + off);
            }
#pragma unroll
            for (int nf2 = 0; nf2 < 2; ++nf2) {
                const uint32_t off =
                    SW128((uint32_t)((n0w + nf2 * 16 + b_lr) * 128 + kf * 32 + b_lc));
                ldsm_x4(bh[nf2], bhb + off);
                ldsm_x4(bl[nf2], blb + off);
            }
#pragma unroll
            for (int mf = 0; mf < 4; ++mf)
#pragma unroll
                for (int nf = 0; nf < 4; ++nf) {
                    const uint32_t* bhp = &bh[nf >> 1][(nf & 1) * 2];
                    const uint32_t* blp = &bl[nf >> 1][(nf & 1) * 2];
                    mma_bf16(acc[mf][nf], ah[mf], bhp);
                    mma_bf16(acc[mf][nf], ah[mf], blp);
                    mma_bf16(acc[mf][nf], al[mf], bhp);
                }
        }
        __syncthreads();
    }

#pragma unroll
    for (int mf = 0; mf < 4; ++mf) {
        const int rg = row0 + m0w + mf * 16 + (lane >> 2);
#pragma unroll
        for (int nf = 0; nf < 4; ++nf) {
            const int cg = n0g + n0w + nf * 8 + ((lane & 3) << 1);
            *(float2*)&g_xproj[(size_t)rg * GG + cg] =
                make_float2(acc[mf][nf][0], acc[mf][nf][1]);
            *(float2*)&g_xproj[(size_t)(rg + 8) * GG + cg] =
                make_float2(acc[mf][nf][2], acc[mf][nf][3]);
        }
    }
}

// ---------------------------------------------------------------------------
// forget gates: block = 64 bt rows; sig tile in smem, fk column in registers.
// ---------------------------------------------------------------------------
__global__ __launch_bounds__(256) void fgate_kernel(const float* __restrict__ sig,
                                                    const float* __restrict__ fk,
                                                    const float* __restrict__ bias) {
    __shared__ float ss[64 * 20];
    const int tid = threadIdx.x;
    const int bt0 = blockIdx.x * 64;

    for (int i = tid; i < 64 * 20; i += 256)
        ss[i] = sig[(size_t)bt0 * 20 + i];

    const int u    = tid & 127;
    const int bsub = tid >> 7;

    float wk[20];
#pragma unroll
    for (int k = 0; k < 20; ++k) wk[k] = __ldg(&fk[k * UU + u]);
    const float bf = bias[UU + u];

    __syncthreads();

#pragma unroll 4
    for (int i = 0; i < 32; ++i) {
        const int bt = bsub * 32 + i;
        float s = bf;
        const float* sr = ss + bt * 20;
#pragma unroll
        for (int k = 0; k < 20; ++k) s = fmaf(sr[k], wk[k], s);
        g_fg[(size_t)(bt0 + bt) * UU + u] = fsig(s);
    }
}

// ---------------------------------------------------------------------------
// HMMA scan, in-register combine, DOUBLE-BUFFERED A to avoid the RAW race.
// 32 blocks x 8 batches, 256 threads. Warp w owns u-slice [16w,16w+16) in all
// three gate regions: col(nc) = (nc>>1)*128 + w*16 + (nc&1)*8.
// Iteration t: reads As[t&1] (h(t-1)), writes As[(t+1)&1] (h(t)). The single
// top-of-loop barrier orders (all of iter t-1) before (writes of iter t).
// ---------------------------------------------------------------------------
#define XS_ROW 388           // floats per batch row (mod 32 == 4 -> no conflicts)
#define XS_F   (8 * XS_ROW)  // 3104
#define FS_ROW 132
#define FS_F   (8 * FS_ROW)  // 1056
#define AS_W   (16 * 68)     // 1088 u32 per buffer
#define XS_OFF 0
#define FS_OFF (2 * XS_F)
#define AS_OFF (2 * XS_F + 2 * FS_F)
#define SCAN_F (AS_OFF + 2 * AS_W)

__global__ __launch_bounds__(256, 1) void scan_mma(const float* __restrict__ bias,
                                                   float* __restrict__ out) {
    __shared__ float sm[SCAN_F];
    float* xs = sm + XS_OFF;
    float* fs = sm + FS_OFF;
    uint32_t* As = (uint32_t*)(sm + AS_OFF);
    const uint32_t smu = s2u(sm);

    const int tid  = threadIdx.x;
    const int wid  = tid >> 5;
    const int lane = tid & 31;
    const int b0g  = blockIdx.x * 8;

    for (int i = tid; i < 2 * AS_W; i += 256) As[i] = 0;

    // rk B-fragments: col n = (nc>>1)*128 + wid*16 + (nc&1)*8 + (lane>>2)
    uint32_t wfr[8][6][2];
#pragma unroll
    for (int kc = 0; kc < 8; ++kc)
#pragma unroll
        for (int nc = 0; nc < 6; ++nc) {
            const int n = (nc >> 1) * 128 + wid * 16 + (nc & 1) * 8 + (lane >> 2);
            const int k = kc * 16 + (lane & 3) * 2;
            wfr[kc][nc][0] = *(const uint32_t*)&g_rk[(size_t)n * UU + k];
            wfr[kc][nc][1] = *(const uint32_t*)&g_rk[(size_t)n * UU + k + 8];
        }

    float bb0[6], bb1[6], pp[6];
#pragma unroll
    for (int nc = 0; nc < 6; ++nc) {
        const int c = (nc >> 1) * 128 + wid * 16 + (nc & 1) * 8 + (lane & 3) * 2;
        bb0[nc] = (c < UU) ? bias[c] : bias[c + UU];
        bb1[nc] = (c + 1 < UU) ? bias[c + 1] : bias[c + 1 + UU];
        pp[nc]  = ((nc >> 1) == 1) ? 1.0f : 0.5f;
    }

    float cst[4] = {0.f, 0.f, 0.f, 0.f};   // c for u0,u1,u8,u9

#define PREFETCH(t)                                                            \
    {                                                                          \
        const int _buf = (t) & 1;                                              \
        _Pragma("unroll")                                                      \
        for (int k2 = 0; k2 < 3; ++k2) {                                       \
            const int id = tid + k2 * 256;                                     \
            const int r = id / 96, o = id % 96;                                \
            cp16(smu + (XS_OFF + _buf * XS_F + r * XS_ROW + o * 4) * 4,        \
                 &g_xproj[((size_t)(b0g + r) * TT + (t)) * GG + o * 4]);       \
        }                                                                      \
        cp16(smu + (FS_OFF + ((t) & 1) * FS_F + (tid >> 5) * FS_ROW +          \
                    (tid & 31) * 4) * 4,                                       \
             &g_fg[((size_t)(b0g + (tid >> 5)) * TT + (t)) * UU +              \
                   (tid & 31) * 4]);                                           \
        cp_commit();                                                           \
    }

    PREFETCH(0);

    const int arow = (lane >> 2) * 68 + (lane & 3);
    const int ucol = wid * 16 + (lane & 3) * 2;
    const int brow = lane >> 2;

    for (int t = 0; t < TT; ++t) {
        cp_wait<0>();
        __syncthreads();   // x/f(t) ready; all warps finished iter t-1

        const uint32_t* Ar = As + (t & 1) * AS_W;        // h(t-1)
        uint32_t* Aw = As + ((t + 1) & 1) * AS_W;        // h(t)

        // acc init from x_proj
        const float* xb = xs + (t & 1) * XS_F + brow * XS_ROW;
        float acc[6][4];
#pragma unroll
        for (int nc = 0; nc < 6; ++nc) {
            const float2 xv =
                *(const float2*)&xb[(nc >> 1) * 128 + ucol + (nc & 1) * 8];
            acc[nc][0] = xv.x; acc[nc][1] = xv.y;
            acc[nc][2] = 0.f;  acc[nc][3] = 0.f;
        }

        if (t + 1 < TT) PREFETCH(t + 1);

        // gates = [h_hi; h_lo] @ rk
#pragma unroll
        for (int kc = 0; kc < 8; ++kc) {
            uint32_t af[4];
            const int base = arow + kc * 8;
            af[0] = Ar[base];
            af[1] = Ar[base + 8 * 68];
            af[2] = Ar[base + 4];
            af[3] = Ar[base + 8 * 68 + 4];
#pragma unroll
            for (int nc = 0; nc < 6; ++nc)
                mma_bf16(acc[nc], af, wfr[kc][nc]);
        }

        // fold + bias + activation, all in registers
        float gv[6][2];
#pragma unroll
        for (int nc = 0; nc < 6; ++nc) {
            const float p = pp[nc], q = 1.0f - p;
            const float g0 = acc[nc][0] + acc[nc][2] + bb0[nc];
            const float g1 = acc[nc][1] + acc[nc][3] + bb1[nc];
            gv[nc][0] = fmaf(tanh_apx(g0 * p), p, q);
            gv[nc][1] = fmaf(tanh_apx(g1 * p), p, q);
        }

        // in-register combine for (batch=brow, u = ucol+{0,1,8,9})
        const float* fr = fs + (t & 1) * FS_F + brow * FS_ROW + ucol;
        const float2 fA = *(const float2*)&fr[0];
        const float2 fB = *(const float2*)&fr[8];
        cst[0] = fmaf(fA.x, cst[0], gv[0][0] * gv[2][0]);
        cst[1] = fmaf(fA.y, cst[1], gv[0][1] * gv[2][1]);
        cst[2] = fmaf(fB.x, cst[2], gv[1][0] * gv[3][0]);
        cst[3] = fmaf(fB.y, cst[3], gv[1][1] * gv[3][1]);
        const float h0 = gv[4][0] * tanh_apx(cst[0]);
        const float h1 = gv[4][1] * tanh_apx(cst[1]);
        const float h2 = gv[5][0] * tanh_apx(cst[2]);
        const float h3 = gv[5][1] * tanh_apx(cst[3]);

        float* orow = &out[((size_t)(b0g + brow) * TT + t) * UU + ucol];
        *(float2*)&orow[0] = make_float2(h0, h1);
        *(float2*)&orow[8] = make_float2(h2, h3);

        // write h(t) as bf16 hi/lo A-rows into the OTHER buffer
        const __nv_bfloat16 h0h = __float2bfloat16(h0);
        const __nv_bfloat16 h1h = __float2bfloat16(h1);
        const __nv_bfloat16 h2h = __float2bfloat16(h2);
        const __nv_bfloat16 h3h = __float2bfloat16(h3);
        const __nv_bfloat16 h0l = __float2bfloat16(h0 - __bfloat162float(h0h));
        const __nv_bfloat16 h1l = __float2bfloat16(h1 - __bfloat162float(h1h));
        const __nv_bfloat16 h2l = __float2bfloat16(h2 - __bfloat162float(h2h));
        const __nv_bfloat16 h3l = __float2bfloat16(h3 - __bfloat162float(h3h));
        const int w0 = brow * 68 + wid * 8 + (lane & 3);
        Aw[w0]     = (uint32_t)*(const unsigned short*)&h0h |
                     ((uint32_t)*(const unsigned short*)&h1h << 16);
        Aw[w0 + 4] = (uint32_t)*(const unsigned short*)&h2h |
                     ((uint32_t)*(const unsigned short*)&h3h << 16);
        Aw[w0 + 8 * 68]     = (uint32_t)*(const unsigned short*)&h0l |
                              ((uint32_t)*(const unsigned short*)&h1l << 16);
        Aw[w0 + 8 * 68 + 4] = (uint32_t)*(const unsigned short*)&h2l |
                              ((uint32_t)*(const unsigned short*)&h3l << 16);
    }
}

// ---------------------------------------------------------------------------
extern "C" void kernel_launch(void* const* d_in, const int* in_sizes, int n_in,
                              void* d_out, int out_size) {
    const float* inputs     = (const float*)d_in[0];
    const float* signatures = (const float*)d_in[1];
    const float* ikern      = (const float*)d_in[2];
    const float* rkern      = (const float*)d_in[3];
    const float* fkern      = (const float*)d_in[4];
    const float* bias       = (const float*)d_in[5];
    float* out = (float*)d_out;

    (void)in_sizes; (void)n_in; (void)out_size;

    cudaFuncSetAttribute(gemm_mma,
                         cudaFuncAttributeMaxDynamicSharedMemorySize, GEMM_SMEM);

    convert_a<<<(MM * DD) / 4 / 256, 256>>>(inputs);
    convert_b<<<GG, DD>>>(ikern);
    convert_rk<<<GG, UU>>>(rkern);
    fgate_kernel<<<MM / 64, 256>>>(signatures, fkern, bias);
    gemm_mma<<<dim3(GG / 128, MM / 128), 256, GEMM_SMEM>>>();
    scan_mma<<<BB / 8, 256>>>(bias, out);
}